// round 3
// baseline (speedup 1.0000x reference)
#include <cuda_runtime.h>

// Problem constants
#define D 256
#define EPS 1e-8f
#define TPB 256
#define MAIN_BLOCKS 1024

// Precomputed per-node 1/max(||emb_row * w||, eps)
__device__ float g_inv[100000];

// ---------------------------------------------------------------------------
// Kernel 1: per-node inverse clamped norm. One warp per node, coalesced rows.
// ---------------------------------------------------------------------------
__global__ void norm_kernel(const float* __restrict__ emb,
                            const float* __restrict__ w, int nNodes) {
    int gw   = (blockIdx.x * blockDim.x + threadIdx.x) >> 5;
    int lane = threadIdx.x & 31;
    if (gw >= nNodes) return;

    const float4* row = (const float4*)(emb + (size_t)gw * D);
    const float4* wv  = (const float4*)w;
    float4 e0 = row[lane],      w0 = wv[lane];
    float4 e1 = row[lane + 32], w1 = wv[lane + 32];

    float t, acc = 0.f;
    t = e0.x * w0.x; acc = fmaf(t, t, acc);
    t = e0.y * w0.y; acc = fmaf(t, t, acc);
    t = e0.z * w0.z; acc = fmaf(t, t, acc);
    t = e0.w * w0.w; acc = fmaf(t, t, acc);
    t = e1.x * w1.x; acc = fmaf(t, t, acc);
    t = e1.y * w1.y; acc = fmaf(t, t, acc);
    t = e1.z * w1.z; acc = fmaf(t, t, acc);
    t = e1.w * w1.w; acc = fmaf(t, t, acc);

    #pragma unroll
    for (int off = 16; off; off >>= 1)
        acc += __shfl_xor_sync(0xffffffffu, acc, off);

    if (lane == 0) {
        float n = fmaxf(sqrtf(acc), EPS);
        g_inv[gw] = 1.0f / n;
    }
}

// ---------------------------------------------------------------------------
// Kernel 2: fused edge kernel.
//   Phase 1 (warp-per-edge): coalesced gather of both rows, weighted dot,
//     cos = dot * inv1 * inv2. Lane k keeps edge (base+k)'s (cos, dot).
//   Phase 2 (thread-per-edge): 2->64->32->1 MLP entirely in registers,
//     weights broadcast from shared (conflict-free).
// ---------------------------------------------------------------------------
__global__ void __launch_bounds__(TPB)
edge_kernel(const int2* __restrict__ edge,   // int32 pairs (JAX downcasts int64)
            const float* __restrict__ emb,
            const float* __restrict__ w,
            const float* __restrict__ W1,    // [64,2]
            const float* __restrict__ b1,    // [64]
            const float* __restrict__ W2,    // [32,64]
            const float* __restrict__ b2,    // [32]
            const float* __restrict__ Wp,    // [32]
            const float* __restrict__ bp,    // [1]
            float* __restrict__ out,
            int E, int totalWarps)
{
    __shared__ float  s_w2[D];        // weight_vec squared
    __shared__ float4 s_l1[64];       // (W1[j][0], W1[j][1], b1[j], 0)
    __shared__ float  s_W2T[64][32];  // W2 transposed: [j][i]
    __shared__ float  s_b2[32];
    __shared__ float  s_Wp[32];
    __shared__ float  s_bp;

    int tid = threadIdx.x;
    for (int i = tid; i < D; i += TPB) { float v = w[i]; s_w2[i] = v * v; }
    for (int i = tid; i < 64; i += TPB)
        s_l1[i] = make_float4(W1[2*i], W1[2*i + 1], b1[i], 0.f);
    for (int i = tid; i < 2048; i += TPB) {
        int r = i & 31;        // output index i (0..31)
        int c = i >> 5;        // hidden index j (0..63)
        s_W2T[c][r] = W2[r * 64 + c];
    }
    if (tid < 32) { s_b2[tid] = b2[tid]; s_Wp[tid] = Wp[tid]; }
    if (tid == 0) s_bp = bp[0];
    __syncthreads();

    int lane  = tid & 31;
    int gwarp = (blockIdx.x * TPB + tid) >> 5;

    // Per-lane squared-weight slice: dims [4*lane..4*lane+3] and [+128..]
    const float4* w2v = (const float4*)s_w2;
    float4 q0 = w2v[lane];
    float4 q1 = w2v[lane + 32];

    for (long base = (long)gwarp * 32; base < E; base += (long)totalWarps * 32) {
        float myCos = 0.f, myDot = 0.f;
        int nE = E - (int)base;
        if (nE > 32) nE = 32;

        // ---- Phase 1: warp-collective dot/cos for up to 32 edges ----
        for (int k = 0; k < nE; k++) {
            int e = (int)base + k;
            int2 ep = edge[e];
            int n0 = ep.x, n1 = ep.y;

            const float4* r0 = (const float4*)(emb + (size_t)n0 * D);
            const float4* r1 = (const float4*)(emb + (size_t)n1 * D);
            float4 a0 = r0[lane],      c0 = r1[lane];
            float4 a1 = r0[lane + 32], c1 = r1[lane + 32];

            float acc = 0.f, m;
            m = a0.x * c0.x; acc = fmaf(q0.x, m, acc);
            m = a0.y * c0.y; acc = fmaf(q0.y, m, acc);
            m = a0.z * c0.z; acc = fmaf(q0.z, m, acc);
            m = a0.w * c0.w; acc = fmaf(q0.w, m, acc);
            m = a1.x * c1.x; acc = fmaf(q1.x, m, acc);
            m = a1.y * c1.y; acc = fmaf(q1.y, m, acc);
            m = a1.z * c1.z; acc = fmaf(q1.z, m, acc);
            m = a1.w * c1.w; acc = fmaf(q1.w, m, acc);

            #pragma unroll
            for (int off = 16; off; off >>= 1)
                acc += __shfl_xor_sync(0xffffffffu, acc, off);

            float cs = acc * g_inv[n0] * g_inv[n1];
            if (lane == k) { myCos = cs; myDot = acc; }
        }

        // ---- Phase 2: thread-per-edge MLP ----
        int e = (int)base + lane;
        if (e < E) {
            float h2[32];
            #pragma unroll
            for (int i = 0; i < 32; i++) h2[i] = s_b2[i];

            #pragma unroll 2
            for (int j = 0; j < 64; j++) {
                float4 c = s_l1[j];
                float hj = fmaxf(fmaf(myCos, c.x, fmaf(myDot, c.y, c.z)), 0.f);
                const float* col = s_W2T[j];
                #pragma unroll
                for (int i = 0; i < 32; i++)
                    h2[i] = fmaf(col[i], hj, h2[i]);
            }

            float p = s_bp;
            #pragma unroll
            for (int i = 0; i < 32; i++)
                p = fmaf(s_Wp[i], fmaxf(h2[i], 0.f), p);

            out[e] = p;
        }
    }
}

// ---------------------------------------------------------------------------
// Launch
// ---------------------------------------------------------------------------
extern "C" void kernel_launch(void* const* d_in, const int* in_sizes, int n_in,
                              void* d_out, int out_size) {
    const int2*  edge = (const int2*)d_in[0];     // int32 [E,2]
    const float* emb  = (const float*)d_in[1];    // [N,256]
    const float* wv   = (const float*)d_in[2];    // [1,256]
    const float* W1   = (const float*)d_in[3];    // [64,2]
    const float* b1   = (const float*)d_in[4];    // [64]
    const float* W2   = (const float*)d_in[5];    // [32,64]
    const float* b2   = (const float*)d_in[6];    // [32]
    const float* Wp   = (const float*)d_in[7];    // [1,32]
    const float* bp   = (const float*)d_in[8];    // [1]
    float* out = (float*)d_out;

    int E      = in_sizes[0] / 2;
    int nNodes = in_sizes[1] / D;

    int normBlocks = (nNodes * 32 + TPB - 1) / TPB;
    norm_kernel<<<normBlocks, TPB>>>(emb, wv, nNodes);

    int totalWarps = MAIN_BLOCKS * (TPB / 32);
    edge_kernel<<<MAIN_BLOCKS, TPB>>>(edge, emb, wv, W1, b1, W2, b2, Wp, bp,
                                      out, E, totalWarps);
}

// round 4
// speedup vs baseline: 1.4724x; 1.4724x over previous
#include <cuda_runtime.h>

// Problem constants
#define D 256
#define EPS 1e-8f
#define TPB 256
#define MAIN_BLOCKS 1024

// Precomputed per-node 1/max(||emb_row * w||, eps)
__device__ float g_inv[100000];

// ---------------------------------------------------------------------------
// Kernel 1: per-node inverse clamped norm. One warp per node, coalesced rows.
// ---------------------------------------------------------------------------
__global__ void norm_kernel(const float* __restrict__ emb,
                            const float* __restrict__ w, int nNodes) {
    int gw   = (blockIdx.x * blockDim.x + threadIdx.x) >> 5;
    int lane = threadIdx.x & 31;
    if (gw >= nNodes) return;

    const float4* row = (const float4*)(emb + (size_t)gw * D);
    const float4* wv  = (const float4*)w;
    float4 e0 = row[lane],      w0 = wv[lane];
    float4 e1 = row[lane + 32], w1 = wv[lane + 32];

    float t, acc = 0.f;
    t = e0.x * w0.x; acc = fmaf(t, t, acc);
    t = e0.y * w0.y; acc = fmaf(t, t, acc);
    t = e0.z * w0.z; acc = fmaf(t, t, acc);
    t = e0.w * w0.w; acc = fmaf(t, t, acc);
    t = e1.x * w1.x; acc = fmaf(t, t, acc);
    t = e1.y * w1.y; acc = fmaf(t, t, acc);
    t = e1.z * w1.z; acc = fmaf(t, t, acc);
    t = e1.w * w1.w; acc = fmaf(t, t, acc);

    #pragma unroll
    for (int off = 16; off; off >>= 1)
        acc += __shfl_xor_sync(0xffffffffu, acc, off);

    if (lane == 0) {
        float n = fmaxf(sqrtf(acc), EPS);
        g_inv[gw] = 1.0f / n;
    }
}

// ---------------------------------------------------------------------------
// Kernel 2: fused edge kernel.
//   Phase 1: 8 lanes per edge, 4 edges concurrently per warp. Sublane s
//     covers dims [32s, 32s+32). 3-step xor-shfl reduce within 8 lanes.
//     Dots staged via shared; each lane then owns edge base+lane.
//   Phase 2 (thread-per-edge): 2->64->32->1 MLP entirely in registers,
//     weights broadcast from shared (conflict-free).
// ---------------------------------------------------------------------------
__global__ void __launch_bounds__(TPB, 3)
edge_kernel(const int2* __restrict__ edge,   // int32 pairs
            const float* __restrict__ emb,
            const float* __restrict__ w,
            const float* __restrict__ W1,    // [64,2]
            const float* __restrict__ b1,    // [64]
            const float* __restrict__ W2,    // [32,64]
            const float* __restrict__ b2,    // [32]
            const float* __restrict__ Wp,    // [32]
            const float* __restrict__ bp,    // [1]
            float* __restrict__ out,
            int E, int totalWarps)
{
    __shared__ float  s_w2[D];            // weight_vec squared
    __shared__ float4 s_l1[64];           // (W1[j][0], W1[j][1], b1[j], 0)
    __shared__ float  s_W2T[64][32];      // W2 transposed: [j][i]
    __shared__ float  s_b2[32];
    __shared__ float  s_Wp[32];
    __shared__ float  s_bp;
    __shared__ float  s_dot[TPB / 32][32];  // per-warp dot staging

    int tid = threadIdx.x;
    for (int i = tid; i < D; i += TPB) { float v = w[i]; s_w2[i] = v * v; }
    for (int i = tid; i < 64; i += TPB)
        s_l1[i] = make_float4(W1[2*i], W1[2*i + 1], b1[i], 0.f);
    for (int i = tid; i < 2048; i += TPB) {
        int r = i & 31;        // output index i (0..31)
        int c = i >> 5;        // hidden index j (0..63)
        s_W2T[c][r] = W2[r * 64 + c];
    }
    if (tid < 32) { s_b2[tid] = b2[tid]; s_Wp[tid] = Wp[tid]; }
    if (tid == 0) s_bp = bp[0];
    __syncthreads();

    int lane  = tid & 31;
    int wid   = tid >> 5;          // warp within block
    int g     = lane >> 3;         // edge-group 0..3
    int s     = lane & 7;          // sublane within group
    int gwarp = (blockIdx.x * TPB + tid) >> 5;

    const float4* w2v = (const float4*)s_w2;

    for (long base = (long)gwarp * 32; base < E; base += (long)totalWarps * 32) {
        // Cooperative edge + inv-norm load: lane owns edge base+lane.
        int e  = (int)base + lane;
        int ce = e < E ? e : E - 1;
        int2 ep = edge[ce];
        float invp = g_inv[ep.x] * g_inv[ep.y];

        // ---- Phase 1: 8 iterations, 4 edges each ----
        #pragma unroll
        for (int k = 0; k < 8; k++) {
            int src = k * 4 + g;
            int n0 = __shfl_sync(0xffffffffu, ep.x, src);
            int n1 = __shfl_sync(0xffffffffu, ep.y, src);

            const float4* r0 = (const float4*)(emb + (size_t)n0 * D);
            const float4* r1 = (const float4*)(emb + (size_t)n1 * D);

            float acc0 = 0.f, acc1 = 0.f, acc2 = 0.f, acc3 = 0.f;
            #pragma unroll
            for (int t = 0; t < 8; t += 4) {
                float4 a0 = r0[s + 8*(t+0)], c0 = r1[s + 8*(t+0)], q0 = w2v[s + 8*(t+0)];
                float4 a1 = r0[s + 8*(t+1)], c1 = r1[s + 8*(t+1)], q1 = w2v[s + 8*(t+1)];
                float4 a2 = r0[s + 8*(t+2)], c2 = r1[s + 8*(t+2)], q2 = w2v[s + 8*(t+2)];
                float4 a3 = r0[s + 8*(t+3)], c3 = r1[s + 8*(t+3)], q3 = w2v[s + 8*(t+3)];

                acc0 = fmaf(q0.x, a0.x * c0.x, acc0);
                acc0 = fmaf(q0.y, a0.y * c0.y, acc0);
                acc0 = fmaf(q0.z, a0.z * c0.z, acc0);
                acc0 = fmaf(q0.w, a0.w * c0.w, acc0);
                acc1 = fmaf(q1.x, a1.x * c1.x, acc1);
                acc1 = fmaf(q1.y, a1.y * c1.y, acc1);
                acc1 = fmaf(q1.z, a1.z * c1.z, acc1);
                acc1 = fmaf(q1.w, a1.w * c1.w, acc1);
                acc2 = fmaf(q2.x, a2.x * c2.x, acc2);
                acc2 = fmaf(q2.y, a2.y * c2.y, acc2);
                acc2 = fmaf(q2.z, a2.z * c2.z, acc2);
                acc2 = fmaf(q2.w, a2.w * c2.w, acc2);
                acc3 = fmaf(q3.x, a3.x * c3.x, acc3);
                acc3 = fmaf(q3.y, a3.y * c3.y, acc3);
                acc3 = fmaf(q3.z, a3.z * c3.z, acc3);
                acc3 = fmaf(q3.w, a3.w * c3.w, acc3);
            }
            float acc = (acc0 + acc1) + (acc2 + acc3);

            // reduce within 8-lane group (xor 4,2,1 stays in-group)
            acc += __shfl_xor_sync(0xffffffffu, acc, 4);
            acc += __shfl_xor_sync(0xffffffffu, acc, 2);
            acc += __shfl_xor_sync(0xffffffffu, acc, 1);

            if (s == 0) s_dot[wid][k * 4 + g] = acc;
        }
        __syncwarp();

        float myDot = s_dot[wid][lane];
        float myCos = myDot * invp;

        // ---- Phase 2: thread-per-edge MLP ----
        if (e < E) {
            float h2[32];
            #pragma unroll
            for (int i = 0; i < 32; i++) h2[i] = s_b2[i];

            #pragma unroll 2
            for (int j = 0; j < 64; j++) {
                float4 c = s_l1[j];
                float hj = fmaxf(fmaf(myCos, c.x, fmaf(myDot, c.y, c.z)), 0.f);
                const float* col = s_W2T[j];
                #pragma unroll
                for (int i = 0; i < 32; i++)
                    h2[i] = fmaf(col[i], hj, h2[i]);
            }

            float p = s_bp;
            #pragma unroll
            for (int i = 0; i < 32; i++)
                p = fmaf(s_Wp[i], fmaxf(h2[i], 0.f), p);

            out[e] = p;
        }
        __syncwarp();
    }
}

// ---------------------------------------------------------------------------
// Launch
// ---------------------------------------------------------------------------
extern "C" void kernel_launch(void* const* d_in, const int* in_sizes, int n_in,
                              void* d_out, int out_size) {
    const int2*  edge = (const int2*)d_in[0];     // int32 [E,2]
    const float* emb  = (const float*)d_in[1];    // [N,256]
    const float* wv   = (const float*)d_in[2];    // [1,256]
    const float* W1   = (const float*)d_in[3];    // [64,2]
    const float* b1   = (const float*)d_in[4];    // [64]
    const float* W2   = (const float*)d_in[5];    // [32,64]
    const float* b2   = (const float*)d_in[6];    // [32]
    const float* Wp   = (const float*)d_in[7];    // [1,32]
    const float* bp   = (const float*)d_in[8];    // [1]
    float* out = (float*)d_out;

    int E      = in_sizes[0] / 2;
    int nNodes = in_sizes[1] / D;

    int normBlocks = (nNodes * 32 + TPB - 1) / TPB;
    norm_kernel<<<normBlocks, TPB>>>(emb, wv, nNodes);

    int totalWarps = MAIN_BLOCKS * (TPB / 32);
    edge_kernel<<<MAIN_BLOCKS, TPB>>>(edge, emb, wv, W1, b1, W2, b2, Wp, bp,
                                      out, E, totalWarps);
}